// round 2
// baseline (speedup 1.0000x reference)
#include <cuda_runtime.h>

// Problem constants
#define B_   32
#define T_   512
#define IN_  512
#define OUT_ 512
#define LH_  512
#define OUT_OFS (B_ * T_ * OUT_)          // 8388608: start of h_n in d_out
#define HN_ELEMS (4 * B_ * LH_)           // 65536

#define NB   148                          // blocks == persistent CTAs (<= SM count)
#define NTPB 1024
#define NT   (NB * NTPB)

// ---------------------------------------------------------------------------
// Persistent device state (static __device__ arrays: allowed scratch).
// Activations transposed + k-quad interleaved: [k/4][b][4] so 32 lanes (b)
// load 4 consecutive k values each with one coalesced LDG.128.
// ---------------------------------------------------------------------------
__device__ __align__(16) float g_xT4[T_][128][B_][4];    // 32 MB
__device__ __align__(16) float g_h0T[2][256][B_][4];     // [parity][row4][b][4], row = dir*512+j
__device__ __align__(16) float g_h1T[2][256][B_][4];
__device__ __align__(16) float g_prevT[128][B_][4];      // pred feedback
__device__ float g_c[2][2][LH_][B_];                     // [layer][dir][j][b]

// Global software barrier state (zero-initialized at module load)
__device__ unsigned g_count;
__device__ volatile unsigned g_gen;

__device__ __forceinline__ float sigmoidf_(float x) {
    return 1.0f / (1.0f + __expf(-x));
}

// Grid-wide sense-reversing barrier. All NB blocks are co-resident (1 CTA/SM,
// grid == 148 <= SM count), so spin-wait cannot deadlock. Works across graph
// replays: the generation counter just keeps incrementing (unsigned wrap ok),
// g_count returns to 0 at every release.
__device__ __forceinline__ void gbar() {
    __syncthreads();
    if (threadIdx.x == 0) {
        unsigned gen = g_gen;
        __threadfence();                       // release prior writes (gpu scope)
        if (atomicAdd(&g_count, 1u) == NB - 1) {
            g_count = 0;
            __threadfence();
            g_gen = gen + 1;                   // release
        } else {
            while (g_gen == gen) { __nanosleep(32); }
        }
        __threadfence();                       // acquire
    }
    __syncthreads();
}

// ---------------------------------------------------------------------------
// Gates + LSTM cell update for one layer (both directions), one timestep.
// 1024 (d,j) groups x 128 threads (32 b x 4 gates). Each block takes 7 groups
// (148*7 = 1036 >= 1024). Weight loads are warp-uniform (broadcast);
// activation loads are coalesced LDG.128.
// ---------------------------------------------------------------------------
template <int LYR>
__device__ __forceinline__ void gates_stage(
    int t, int par,
    const float* __restrict__ W_ih, const float* __restrict__ W_hh,
    const float* __restrict__ b_ih, const float* __restrict__ b_hh,
    float (*gsh)[4][32])
{
    const int sub  = threadIdx.x >> 7;         // 0..7 (sub 7 idle)
    const int lane = threadIdx.x & 127;
    const int b    = lane & 31;
    const int gate = lane >> 5;                // 0..3 = i,f,g,o
    const int grp  = blockIdx.x * 7 + sub;     // (d,j) group id
    const bool act = (sub < 7) && (grp < 1024);

    float val = 0.0f;
    if (act) {
        const int d = grp >> 9;
        const int j = grp & 511;
        const int wrow = (LYR * 2 + d) * 2048 + gate * 512 + j;
        const float4* __restrict__ wih4 = (const float4*)(W_ih + ((long)wrow << 10));
        const float4* __restrict__ whh4 = (const float4*)(W_hh + ((long)wrow << 9));

        float a0 = b_ih[wrow] + b_hh[wrow];
        float a1 = 0.0f;

        if (LYR == 0) {
            const float4* __restrict__ xs = (const float4*)(&g_xT4[t][0][0][0]) + b;
            #pragma unroll 8
            for (int k = 0; k < 128; k++) {
                float4 w = __ldcs(&wih4[k]); float4 x = xs[k * 32];
                a0 += w.x * x.x; a1 += w.y * x.y;
                a0 += w.z * x.z; a1 += w.w * x.w;
            }
            const float4* __restrict__ ps = (const float4*)(&g_prevT[0][0][0]) + b;
            #pragma unroll 8
            for (int k = 0; k < 128; k++) {
                float4 w = __ldcs(&wih4[128 + k]); float4 x = ps[k * 32];
                a0 += w.x * x.x; a1 += w.y * x.y;
                a0 += w.z * x.z; a1 += w.w * x.w;
            }
        } else {
            const float4* __restrict__ hs = (const float4*)(&g_h0T[par][0][0][0]) + b;
            #pragma unroll 8
            for (int k = 0; k < 256; k++) {
                float4 w = __ldcs(&wih4[k]); float4 x = hs[k * 32];
                a0 += w.x * x.x; a1 += w.y * x.y;
                a0 += w.z * x.z; a1 += w.w * x.w;
            }
        }

        // Recurrent term: own-direction h from previous step (other parity)
        const float4* __restrict__ rs =
            (LYR == 0 ? (const float4*)(&g_h0T[par ^ 1][d * 128][0][0])
                      : (const float4*)(&g_h1T[par ^ 1][d * 128][0][0])) + b;
        #pragma unroll 8
        for (int k = 0; k < 128; k++) {
            float4 w = __ldcs(&whh4[k]); float4 x = rs[k * 32];
            a0 += w.x * x.x; a1 += w.y * x.y;
            a0 += w.z * x.z; a1 += w.w * x.w;
        }
        val = a0 + a1;
    }

    if (act) gsh[sub][gate][b] = val;
    __syncthreads();

    if (act && gate == 0) {
        const int d = grp >> 9;
        const int j = grp & 511;
        float gi = gsh[sub][0][b], gf = gsh[sub][1][b];
        float gg = gsh[sub][2][b], go = gsh[sub][3][b];
        float co = g_c[LYR][d][j][b];
        float cn = sigmoidf_(gf) * co + sigmoidf_(gi) * tanhf(gg);
        float hn = sigmoidf_(go) * tanhf(cn);
        g_c[LYR][d][j][b] = cn;
        int row = d * 512 + j;
        float* dst = (LYR == 0 ? &g_h0T[par][0][0][0] : &g_h1T[par][0][0][0]);
        dst[((row >> 2) * 32 + b) * 4 + (row & 3)] = hn;
    }
    // gsh reuse is guarded by the gbar() that follows every stage.
}

// ---------------------------------------------------------------------------
// Single persistent kernel: init -> transpose -> 512 x (L0 | L1 | FC) -> final.
// One graph node total (avoids the multi-node graph upload buffer that
// violated the device-memory rule in R1).
// ---------------------------------------------------------------------------
__global__ void __launch_bounds__(NTPB, 1) encoder_persistent(
    const float* __restrict__ in_seq,
    const float* __restrict__ W_ih, const float* __restrict__ W_hh,
    const float* __restrict__ b_ih, const float* __restrict__ b_hh,
    const float* __restrict__ W_fc, const float* __restrict__ b_fc,
    float* __restrict__ out)
{
    __shared__ float gsh[8][4][32];
    const int tid = blockIdx.x * NTPB + threadIdx.x;

    // --- init state (must run every replay) ---
    for (int i = tid; i < 2 * 2 * LH_ * B_; i += NT) ((float*)g_c)[i] = 0.0f;
    for (int i = tid; i < 2 * 256 * B_ * 4; i += NT) {
        ((float*)g_h0T)[i] = 0.0f;
        ((float*)g_h1T)[i] = 0.0f;
    }
    for (int i = tid; i < 128 * B_ * 4; i += NT) ((float*)g_prevT)[i] = 0.0f;

    // --- transpose input: [B,T,IN] -> g_xT4[t][k/4][b][k%4] ---
    for (int i = tid; i < T_ * 128 * B_ * 4; i += NT) {
        int c  = i & 3;
        int b  = (i >> 2) & 31;
        int k4 = (i >> 7) & 127;
        int t  = i >> 14;
        ((float*)g_xT4)[i] = in_seq[(b * T_ + t) * IN_ + k4 * 4 + c];
    }
    gbar();

    // --- time loop ---
    for (int t = 0; t < T_; t++) {
        const int par = t & 1;

        gates_stage<0>(t, par, W_ih, W_hh, b_ih, b_hh, gsh);
        gbar();
        gates_stage<1>(t, par, W_ih, W_hh, b_ih, b_hh, gsh);
        gbar();

        // FC head, split-K by 8 with warp-shuffle reduction:
        // thread = (o, b, ks); 131072 threads active.
        if (tid < 131072) {
            const int ks = tid & 7;
            const int ob = tid >> 3;
            const int b  = ob & 31;
            const int o  = ob >> 5;
            const float4* __restrict__ w4 = (const float4*)(W_fc + ((long)o << 10));
            const float4* __restrict__ hs = (const float4*)(&g_h1T[par][0][0][0]) + b;
            float a0 = 0.0f, a1 = 0.0f;
            #pragma unroll 8
            for (int k = 0; k < 32; k++) {
                float4 w = w4[ks * 32 + k];
                float4 x = hs[(ks * 32 + k) * 32];
                a0 += w.x * x.x; a1 += w.y * x.y;
                a0 += w.z * x.z; a1 += w.w * x.w;
            }
            float p = a0 + a1;
            p += __shfl_xor_sync(0xffffffffu, p, 1);
            p += __shfl_xor_sync(0xffffffffu, p, 2);
            p += __shfl_xor_sync(0xffffffffu, p, 4);
            if (ks == 0) {
                p += b_fc[o];
                out[(b * T_ + t) * OUT_ + o] = p;          // outputs[b][t][o]
                g_prevT[o >> 2][b][o & 3] = p;             // feedback (detach)
            }
        }
        gbar();
    }

    // --- final h_n / c_n emission ---
    const int parL = (T_ - 1) & 1;
    for (int i = tid; i < 65536; i += NT) {
        int b = i & 31;
        int j = (i >> 5) & 511;
        int d = (i >> 14) & 1;
        int l = i >> 15;
        int row = d * 512 + j;
        const float* src = (l == 0 ? &g_h0T[parL][0][0][0] : &g_h1T[parL][0][0][0]);
        float h = src[((row >> 2) * 32 + b) * 4 + (row & 3)];
        float c = g_c[l][d][j][b];
        int ofs = ((l * 2 + d) * B_ + b) * LH_ + j;
        out[OUT_OFS + ofs] = h;
        out[OUT_OFS + HN_ELEMS + ofs] = c;
    }
}

// ---------------------------------------------------------------------------
// Inputs (metadata order): input_seq, input_lengths, W_ih, W_hh, b_ih, b_hh,
// W_fc, b_fc. input_lengths == T for all rows (reference ignores it).
// ---------------------------------------------------------------------------
extern "C" void kernel_launch(void* const* d_in, const int* in_sizes, int n_in,
                              void* d_out, int out_size) {
    (void)in_sizes; (void)n_in; (void)out_size;
    const float* in_seq = (const float*)d_in[0];
    const float* W_ih   = (const float*)d_in[2];
    const float* W_hh   = (const float*)d_in[3];
    const float* b_ih   = (const float*)d_in[4];
    const float* b_hh   = (const float*)d_in[5];
    const float* W_fc   = (const float*)d_in[6];
    const float* b_fc   = (const float*)d_in[7];
    float* out = (float*)d_out;

    encoder_persistent<<<NB, NTPB>>>(in_seq, W_ih, W_hh, b_ih, b_hh, W_fc, b_fc, out);
}

// round 5
// speedup vs baseline: 2.7923x; 2.7923x over previous
#include <cuda_runtime.h>

// Problem constants
#define B_   32
#define T_   512
#define IN_  512
#define OUT_ 512
#define LH_  512
#define OUT_OFS (B_ * T_ * OUT_)          // start of h_n in d_out
#define HN_ELEMS (4 * B_ * LH_)           // 65536

#define NB   148
#define NTPB 768
#define NT   (NB * NTPB)

// ---------------------------------------------------------------------------
// Persistent device scratch.
// g_wT[l][k][p]: transposed+permuted gate weights. p = d*2048 + j*4 + gate.
//   k<1024 -> W_ih column k ; k>=1024 -> W_hh column k-1024.
// Activation buffers are [k][b] (b fastest, 128B per k row).
// a0 (layer-0 input, per parity, per dir): k<512 x_t | 512..1023 prev | 1024.. h_rec
// a1 (layer-1 input):                      k<1024 h0 (f|b)           | 1024.. h_rec
// ---------------------------------------------------------------------------
__device__ __align__(16) float g_xT[T_][512][B_];          // 32 MB  [t][k][b]
__device__ __align__(16) float g_wT[2][1536][4096];        // 50 MB
__device__ __align__(16) float g_wfcT[1024][512];          // 2 MB   [k][o]
__device__ __align__(16) float g_bias[2][4096];            // b_ih+b_hh, permuted
__device__ __align__(16) float g_a0[2][2][1536][B_];       // [par][d][k][b]
__device__ __align__(16) float g_a1[2][2][1536][B_];
__device__ __align__(16) float g_afc[1024][B_];
__device__ float g_c[2][2][LH_][B_];                       // [l][d][j][b]

__device__ unsigned g_count;
__device__ volatile unsigned g_gen;

__device__ __forceinline__ float sigmoidf_(float x) {
    return 1.0f / (1.0f + __expf(-x));
}

// Grid-wide sense-reversing barrier (all 148 CTAs co-resident, 1/SM).
__device__ __forceinline__ void gbar() {
    __syncthreads();
    if (threadIdx.x == 0) {
        unsigned gen = g_gen;
        __threadfence();
        if (atomicAdd(&g_count, 1u) == NB - 1) {
            g_count = 0;
            __threadfence();
            g_gen = gen + 1;
        } else {
            while (g_gen == gen) { __nanosleep(32); }
        }
        __threadfence();
    }
    __syncthreads();
}

// ---------------------------------------------------------------------------
// Gate stage for layer L (both dirs): GEMM [4096 rows x K=1536] x [1536 x 32b]
// 128 blocks x 32 rows. Block: 768 threads = 12 k-slices x (8 rowgrp x 8 bgrp),
// micro-tile 4 rows x 4 b. Then SMEM split-K reduce + LSTM cell epilogue.
// ---------------------------------------------------------------------------
template <int L>
__device__ __forceinline__ void gate_stage(int par, float* part) {
    const int blk = blockIdx.x;
    if (blk >= 128) return;           // idle blocks fall through to gbar
    const int tid    = threadIdx.x;
    const int bgrp   = tid & 7;
    const int rowgrp = (tid >> 3) & 7;
    const int slice  = tid >> 6;      // 0..11
    const int d      = blk >> 6;

    const float4* __restrict__ w4 = (const float4*)
        (&g_wT[L][slice * 128][blk * 32 + rowgrp * 4]);
    const float* abase = (L == 0 ? &g_a0[par][d][0][0] : &g_a1[par][d][0][0]);
    const float4* __restrict__ a4 = (const float4*)(abase + slice * 128 * B_ + bgrp * 4);

    float c00=0,c01=0,c02=0,c03=0, c10=0,c11=0,c12=0,c13=0;
    float c20=0,c21=0,c22=0,c23=0, c30=0,c31=0,c32=0,c33=0;

    #pragma unroll 8
    for (int i = 0; i < 128; i++) {
        float4 w = w4[i * 1024];      // wT row stride = 4096 floats
        float4 a = a4[i * 8];         // act row stride = 32 floats
        c00 += w.x*a.x; c01 += w.x*a.y; c02 += w.x*a.z; c03 += w.x*a.w;
        c10 += w.y*a.x; c11 += w.y*a.y; c12 += w.y*a.z; c13 += w.y*a.w;
        c20 += w.z*a.x; c21 += w.z*a.y; c22 += w.z*a.z; c23 += w.z*a.w;
        c30 += w.w*a.x; c31 += w.w*a.y; c32 += w.w*a.z; c33 += w.w*a.w;
    }

    // part[s][r][b], r in 0..31, b in 0..31
    {
        float4* p4 = (float4*)part;
        int base = (slice * 32 + rowgrp * 4) * 32 + bgrp * 4;   // float idx
        p4[(base >> 2) + 0*8]  = make_float4(c00, c01, c02, c03);
        p4[(base >> 2) + 1*8]  = make_float4(c10, c11, c12, c13);
        p4[(base >> 2) + 2*8]  = make_float4(c20, c21, c22, c23);
        p4[(base >> 2) + 3*8]  = make_float4(c30, c31, c32, c33);
    }
    __syncthreads();

    if (tid < 256) {
        const int j8 = tid >> 5;
        const int b  = tid & 31;
        float g[4];
        #pragma unroll
        for (int gate = 0; gate < 4; gate++) {
            int r = j8 * 4 + gate;
            float v = g_bias[L][blk * 32 + r];
            #pragma unroll
            for (int s = 0; s < 12; s++) v += part[(s * 32 + r) * 32 + b];
            g[gate] = v;
        }
        const int j = (blk & 63) * 8 + j8;
        float co = g_c[L][d][j][b];
        float cn = sigmoidf_(g[1]) * co + sigmoidf_(g[0]) * tanhf(g[2]);
        float hn = sigmoidf_(g[3]) * tanhf(cn);
        g_c[L][d][j][b] = cn;
        if (L == 0) {
            g_a1[par][0][d * 512 + j][b] = hn;     // h0 for layer-1 (both dirs read)
            g_a1[par][1][d * 512 + j][b] = hn;
            g_a0[par ^ 1][d][1024 + j][b] = hn;    // h_rec for next step
        } else {
            g_afc[d * 512 + j][b] = hn;            // FC input
            g_a1[par ^ 1][d][1024 + j][b] = hn;    // h_rec for next step
        }
    }
}

// ---------------------------------------------------------------------------
// Single persistent kernel.
// ---------------------------------------------------------------------------
__global__ void __launch_bounds__(NTPB, 1) encoder_persistent(
    const float* __restrict__ in_seq,
    const float* __restrict__ W_ih, const float* __restrict__ W_hh,
    const float* __restrict__ b_ih, const float* __restrict__ b_hh,
    const float* __restrict__ W_fc, const float* __restrict__ b_fc,
    float* __restrict__ out)
{
    __shared__ float part[12 * 32 * 32];     // 48 KB; FC reuses first 32 KB
    const int gtid = blockIdx.x * NTPB + threadIdx.x;

    // ===== init phase (runs every replay) =====
    // 1) xT[t][k][b] <- in_seq[b][t][k]
    for (int i = gtid; i < T_ * 512 * B_; i += NT) {
        int b = i & 31, k = (i >> 5) & 511, t = i >> 14;
        ((float*)g_xT)[i] = in_seq[((b << 9) | t) * 512 + k];
    }
    // 2) gate weights W_ih part: iterate (l,d,gate,j,k4)
    for (int i = gtid; i < 2 * 4096 * 256; i += NT) {
        int k4 = i & 255, rr = i >> 8;
        int l = rr >> 12, dgj = rr & 4095;
        int d = dgj >> 11, gate = (dgj >> 9) & 3, j = dgj & 511;
        int wrow = (l * 2 + d) * 2048 + gate * 512 + j;
        float4 w = ((const float4*)W_ih)[wrow * 256 + k4];
        int p = d * 2048 + j * 4 + gate;
        g_wT[l][k4 * 4 + 0][p] = w.x;
        g_wT[l][k4 * 4 + 1][p] = w.y;
        g_wT[l][k4 * 4 + 2][p] = w.z;
        g_wT[l][k4 * 4 + 3][p] = w.w;
    }
    // 3) gate weights W_hh part
    for (int i = gtid; i < 2 * 4096 * 128; i += NT) {
        int k4 = i & 127, rr = i >> 7;
        int l = rr >> 12, dgj = rr & 4095;
        int d = dgj >> 11, gate = (dgj >> 9) & 3, j = dgj & 511;
        int wrow = (l * 2 + d) * 2048 + gate * 512 + j;
        float4 w = ((const float4*)W_hh)[wrow * 128 + k4];
        int p = d * 2048 + j * 4 + gate;
        g_wT[l][1024 + k4 * 4 + 0][p] = w.x;
        g_wT[l][1024 + k4 * 4 + 1][p] = w.y;
        g_wT[l][1024 + k4 * 4 + 2][p] = w.z;
        g_wT[l][1024 + k4 * 4 + 3][p] = w.w;
    }
    // 4) FC weights: wfcT[k][o]
    for (int i = gtid; i < 512 * 256; i += NT) {
        int k4 = i & 255, o = i >> 8;
        float4 w = ((const float4*)W_fc)[o * 256 + k4];
        g_wfcT[k4 * 4 + 0][o] = w.x;
        g_wfcT[k4 * 4 + 1][o] = w.y;
        g_wfcT[k4 * 4 + 2][o] = w.z;
        g_wfcT[k4 * 4 + 3][o] = w.w;
    }
    // 5) biases (permuted)
    for (int i = gtid; i < 2 * 4096; i += NT) {
        int l = i >> 12, p = i & 4095;
        int d = p >> 11, j = (p >> 2) & 511, gate = p & 3;
        int wrow = (l * 2 + d) * 2048 + gate * 512 + j;
        g_bias[l][p] = b_ih[wrow] + b_hh[wrow];
    }
    // 6) zero initial state: a0[0] prev+hrec, a1[0] hrec, g_c
    for (int i = gtid; i < 2 * 1024 * B_; i += NT) {
        int b = i & 31, kk = (i >> 5) & 1023, d = i >> 15;
        g_a0[0][d][512 + kk][b] = 0.0f;
    }
    for (int i = gtid; i < 2 * 512 * B_; i += NT) {
        int b = i & 31, kk = (i >> 5) & 511, d = i >> 14;
        g_a1[0][d][1024 + kk][b] = 0.0f;
    }
    for (int i = gtid; i < 2 * 2 * LH_ * B_; i += NT) ((float*)g_c)[i] = 0.0f;
    // 7) x_0 into a0[0]
    for (int i = gtid; i < 512 * B_; i += NT) {
        int b = i & 31, k = i >> 5;
        float v = in_seq[(b << 18) + k];   // t = 0
        g_a0[0][0][k][b] = v;
        g_a0[0][1][k][b] = v;
    }
    gbar();

    // ===== time loop =====
    for (int t = 0; t < T_; t++) {
        const int par = t & 1;

        gate_stage<0>(par, part);
        gbar();
        gate_stage<1>(par, part);
        gbar();

        // FC head (blocks 0..63) + x_{t+1} copy (blocks 64..147)
        const int blk = blockIdx.x;
        if (blk < 64) {
            const int tid = threadIdx.x;
            if (tid < 512) {
                const int sub = tid & 15;
                const int slice = tid >> 4;          // 0..31, 32 k each
                const int bgrp = sub & 7;
                const int rowgrp = sub >> 3;         // 0..1
                const float4* __restrict__ w4 = (const float4*)
                    (&g_wfcT[slice * 32][blk * 8 + rowgrp * 4]);
                const float4* __restrict__ a4 = (const float4*)
                    (&g_afc[slice * 32][bgrp * 4]);
                float c00=0,c01=0,c02=0,c03=0, c10=0,c11=0,c12=0,c13=0;
                float c20=0,c21=0,c22=0,c23=0, c30=0,c31=0,c32=0,c33=0;
                #pragma unroll 8
                for (int i = 0; i < 32; i++) {
                    float4 w = w4[i * 128];          // wfcT row stride = 512
                    float4 a = a4[i * 8];
                    c00 += w.x*a.x; c01 += w.x*a.y; c02 += w.x*a.z; c03 += w.x*a.w;
                    c10 += w.y*a.x; c11 += w.y*a.y; c12 += w.y*a.z; c13 += w.y*a.w;
                    c20 += w.z*a.x; c21 += w.z*a.y; c22 += w.z*a.z; c23 += w.z*a.w;
                    c30 += w.w*a.x; c31 += w.w*a.y; c32 += w.w*a.z; c33 += w.w*a.w;
                }
                float4* p4 = (float4*)part;
                int base = (slice * 8 + rowgrp * 4) * 32 + bgrp * 4;
                p4[(base >> 2) + 0*8] = make_float4(c00, c01, c02, c03);
                p4[(base >> 2) + 1*8] = make_float4(c10, c11, c12, c13);
                p4[(base >> 2) + 2*8] = make_float4(c20, c21, c22, c23);
                p4[(base >> 2) + 3*8] = make_float4(c30, c31, c32, c33);
            }
            __syncthreads();
            if (threadIdx.x < 256) {
                const int r = threadIdx.x >> 5;
                const int b = threadIdx.x & 31;
                const int o = blk * 8 + r;
                float v = b_fc[o];
                #pragma unroll
                for (int s = 0; s < 32; s++) v += part[(s * 8 + r) * 32 + b];
                out[((b << 9) | t) * 512 + o] = v;            // outputs[b][t][o]
                g_a0[par ^ 1][0][512 + o][b] = v;             // prev for next step
                g_a0[par ^ 1][1][512 + o][b] = v;
            }
        } else if (t + 1 < T_) {
            // copy x_{t+1} into next-parity act buffers (both dirs)
            int idx = (blk - 64) * NTPB + threadIdx.x;
            if (idx < 4096) {                                 // 512*32/4 float4s
                const float4* xs = (const float4*)(&g_xT[t + 1][0][0]);
                float4 v = xs[idx];
                ((float4*)(&g_a0[par ^ 1][0][0][0]))[idx] = v;
                ((float4*)(&g_a0[par ^ 1][1][0][0]))[idx] = v;
            }
        }
        gbar();
    }

    // ===== final h_n / c_n =====
    // last step t=511 (par=1) wrote h_rec into buffers[0]
    for (int i = gtid; i < 65536; i += NT) {
        int b = i & 31, j = (i >> 5) & 511, d = (i >> 14) & 1, l = i >> 15;
        float h = (l == 0 ? g_a0[0][d][1024 + j][b] : g_a1[0][d][1024 + j][b]);
        float c = g_c[l][d][j][b];
        int ofs = (((l * 2 + d) * B_) + b) * LH_ + j;
        out[OUT_OFS + ofs] = h;
        out[OUT_OFS + HN_ELEMS + ofs] = c;
    }
}

// ---------------------------------------------------------------------------
// Inputs (metadata order): input_seq, input_lengths, W_ih, W_hh, b_ih, b_hh,
// W_fc, b_fc.
// ---------------------------------------------------------------------------
extern "C" void kernel_launch(void* const* d_in, const int* in_sizes, int n_in,
                              void* d_out, int out_size) {
    (void)in_sizes; (void)n_in; (void)out_size;
    encoder_persistent<<<NB, NTPB>>>(
        (const float*)d_in[0],
        (const float*)d_in[2], (const float*)d_in[3],
        (const float*)d_in[4], (const float*)d_in[5],
        (const float*)d_in[6], (const float*)d_in[7],
        (float*)d_out);
}

// round 11
// speedup vs baseline: 4.5597x; 1.6330x over previous
#include <cuda_runtime.h>

// Problem constants
#define B_   32
#define T_   512
#define IN_  512
#define OUT_ 512
#define LH_  512
#define OUT_OFS (B_ * T_ * OUT_)          // start of h_n in d_out
#define HN_ELEMS (4 * B_ * LH_)           // 65536

#define NB   148
#define NTPB 768
#define NT   (NB * NTPB)

// dynamic smem layout (floats)
#define PART_F 12288                      // 12 slices x 32 rows x 32 b
#define WS_F   12288                      // 12 slices x 2 buf x 16 k x 32 rows
#define AS_F   12288                      // 12 slices x 2 buf x 16 k x 32 b
#define SMEM_BYTES ((PART_F + WS_F + AS_F) * 4)   // 147456

// ---------------------------------------------------------------------------
// Persistent device scratch.
// g_wT[l][k][p]: transposed+permuted gate weights. p = d*2048 + j*4 + gate.
//   k<1024 -> W_ih column k ; k>=1024 -> W_hh column k-1024.
// Activation buffers are [k][b] (b fastest, 128B per k row).
// a0 (layer-0 input, per parity, per dir): k<512 x_t | 512..1023 prev | 1024.. h_rec
// a1 (layer-1 input):                      k<1024 h0 (f|b)           | 1024.. h_rec
// ---------------------------------------------------------------------------
__device__ __align__(16) float g_xT[T_][512][B_];          // 32 MB  [t][k][b]
__device__ __align__(16) float g_wT[2][1536][4096];        // 50 MB
__device__ __align__(16) float g_wfcT[1024][512];          // 2 MB   [k][o]
__device__ __align__(16) float g_bias[2][4096];            // b_ih+b_hh, permuted
__device__ __align__(16) float g_a0[2][2][1536][B_];       // [par][d][k][b]
__device__ __align__(16) float g_a1[2][2][1536][B_];
__device__ __align__(16) float g_afc[1024][B_];
__device__ float g_c[2][2][LH_][B_];                       // [l][d][j][b]

__device__ unsigned g_count;
__device__ volatile unsigned g_gen;

__device__ __forceinline__ float sigmoidf_(float x) {
    return 1.0f / (1.0f + __expf(-x));
}

// ---- packed f32x2 helpers (FFMA2 path, sm_103a) ----
__device__ __forceinline__ unsigned long long pk2(float lo, float hi) {
    unsigned long long r;
    asm("mov.b64 %0, {%1, %2};" : "=l"(r) : "f"(lo), "f"(hi));
    return r;
}
__device__ __forceinline__ void ffma2(unsigned long long& d,
                                      unsigned long long a, unsigned long long b) {
    asm("fma.rn.f32x2 %0, %1, %2, %0;" : "+l"(d) : "l"(a), "l"(b));
}
__device__ __forceinline__ float2 upk2(unsigned long long v) {
    float2 f;
    asm("mov.b64 {%0, %1}, %2;" : "=f"(f.x), "=f"(f.y) : "l"(v));
    return f;
}

// ---- cp.async helpers ----
__device__ __forceinline__ void cp16(unsigned s, const float* g) {
    asm volatile("cp.async.cg.shared.global [%0], [%1], 16;"
                 :: "r"(s), "l"(__cvta_generic_to_global(g)) : "memory");
}
__device__ __forceinline__ void cpcommit() {
    asm volatile("cp.async.commit_group;" ::: "memory");
}
__device__ __forceinline__ void cpwait1() {
    asm volatile("cp.async.wait_group 1;" ::: "memory");
}
__device__ __forceinline__ void cpwait0() {
    asm volatile("cp.async.wait_group 0;" ::: "memory");
}
__device__ __forceinline__ void barslice(int sid) {   // 64-thread named barrier
    asm volatile("bar.sync %0, 64;" :: "r"(sid + 1) : "memory");
}
__device__ __forceinline__ unsigned s2u(const void* p) {
    return (unsigned)__cvta_generic_to_shared(p);
}

// Grid-wide sense-reversing barrier (all 148 CTAs co-resident, 1/SM).
__device__ __forceinline__ void gbar() {
    __syncthreads();
    if (threadIdx.x == 0) {
        unsigned gen = g_gen;
        __threadfence();
        if (atomicAdd(&g_count, 1u) == NB - 1) {
            g_count = 0;
            __threadfence();
            g_gen = gen + 1;
        } else {
            while (g_gen == gen) { __nanosleep(32); }
        }
        __threadfence();
    }
    __syncthreads();
}

// ---------------------------------------------------------------------------
// Gate stage for layer L (both dirs): GEMM [4096 rows x K=1536] x [1536 x 32b]
// 128 blocks x 32 rows; 12 k-slices x 64 threads; micro-tile 4 rows x 4 b.
// Operands double-buffered through SMEM via cp.async (chunks of 16 k).
// Core math: packed fma.rn.f32x2 with row-paired accumulators.
// ---------------------------------------------------------------------------
template <int L>
__device__ __forceinline__ void gate_stage(int par, float* part, float* ws, float* as) {
    const int blk = blockIdx.x;
    if (blk >= 128) return;           // idle blocks fall through to gbar
    const int tid    = threadIdx.x;
    const int slice  = tid >> 6;      // 0..11
    const int t64    = tid & 63;
    const int bgrp   = t64 & 7;       // also copy col c
    const int rowgrp = t64 >> 3;      // 0..7, also copy row q
    const int d      = blk >> 6;
    const int pbase  = blk * 32;

    const float* abase = (L == 0 ? &g_a0[par][d][0][0] : &g_a1[par][d][0][0]);
    const float* wsrc  = &g_wT[L][slice * 128 + rowgrp][pbase + 4 * bgrp];
    const float* asrc  = abase + (slice * 128 + rowgrp) * 32 + 4 * bgrp;

    const unsigned dofs = (unsigned)(((slice * 2 * 16 + rowgrp) * 32 + bgrp * 4) * 4);
    const unsigned wd = s2u(ws) + dofs;
    const unsigned ad = s2u(as) + dofs;

    // prefetch chunk 0 -> buf 0  (each thread: rows q and q+8, 16B column c)
    cp16(wd, wsrc);          cp16(wd + 1024, wsrc + 8 * 4096);
    cp16(ad, asrc);          cp16(ad + 1024, asrc + 8 * 32);
    cpcommit();

    unsigned long long A00=0,A01=0,A02=0,A03=0,A10=0,A11=0,A12=0,A13=0;

    const float* wsb0 = ws + slice * 2 * 16 * 32 + rowgrp * 4;
    const float* asb0 = as + slice * 2 * 16 * 32 + bgrp * 4;

    #pragma unroll 1
    for (int ch = 0; ch < 8; ch++) {
        const int buf = ch & 1;
        if (ch < 7) {
            const float* w2 = wsrc + (ch + 1) * (16 * 4096);
            const float* a2 = asrc + (ch + 1) * (16 * 32);
            const unsigned bo = (unsigned)(((ch + 1) & 1) * 2048);
            cp16(wd + bo, w2);  cp16(wd + bo + 1024, w2 + 8 * 4096);
            cp16(ad + bo, a2);  cp16(ad + bo + 1024, a2 + 8 * 32);
            cpcommit();
            cpwait1();
        } else {
            cpwait0();
        }
        barslice(slice);

        const float* wp = wsb0 + buf * (16 * 32);
        const float* ap = asb0 + buf * (16 * 32);
        #pragma unroll
        for (int kk = 0; kk < 16; kk++) {
            float4 w = *(const float4*)(wp + kk * 32);
            float4 a = *(const float4*)(ap + kk * 32);
            unsigned long long w01 = pk2(w.x, w.y), w23 = pk2(w.z, w.w);
            unsigned long long ax = pk2(a.x, a.x), ay = pk2(a.y, a.y);
            unsigned long long az = pk2(a.z, a.z), aw = pk2(a.w, a.w);
            ffma2(A00, w01, ax); ffma2(A01, w01, ay);
            ffma2(A02, w01, az); ffma2(A03, w01, aw);
            ffma2(A10, w23, ax); ffma2(A11, w23, ay);
            ffma2(A12, w23, az); ffma2(A13, w23, aw);
        }
        barslice(slice);
    }

    // partials: A0b = rows (rg*4+0, +1) for batch b ; A1b = rows (+2, +3)
    {
        float2 b0r01 = upk2(A00), b1r01 = upk2(A01), b2r01 = upk2(A02), b3r01 = upk2(A03);
        float2 b0r23 = upk2(A10), b1r23 = upk2(A11), b2r23 = upk2(A12), b3r23 = upk2(A13);
        float4* p4 = (float4*)part;
        int base = ((slice * 32 + rowgrp * 4) * 32 + bgrp * 4) >> 2;
        p4[base + 0 * 8] = make_float4(b0r01.x, b1r01.x, b2r01.x, b3r01.x);
        p4[base + 1 * 8] = make_float4(b0r01.y, b1r01.y, b2r01.y, b3r01.y);
        p4[base + 2 * 8] = make_float4(b0r23.x, b1r23.x, b2r23.x, b3r23.x);
        p4[base + 3 * 8] = make_float4(b0r23.y, b1r23.y, b2r23.y, b3r23.y);
    }
    __syncthreads();

    if (tid < 256) {
        const int j8 = tid >> 5;
        const int b  = tid & 31;
        float g[4];
        #pragma unroll
        for (int gate = 0; gate < 4; gate++) {
            int r = j8 * 4 + gate;
            float v = g_bias[L][blk * 32 + r];
            #pragma unroll
            for (int s = 0; s < 12; s++) v += part[(s * 32 + r) * 32 + b];
            g[gate] = v;
        }
        const int j = (blk & 63) * 8 + j8;
        float co = g_c[L][d][j][b];
        float cn = sigmoidf_(g[1]) * co + sigmoidf_(g[0]) * tanhf(g[2]);
        float hn = sigmoidf_(g[3]) * tanhf(cn);
        g_c[L][d][j][b] = cn;
        if (L == 0) {
            g_a1[par][0][d * 512 + j][b] = hn;     // h0 for layer-1 (both dirs read)
            g_a1[par][1][d * 512 + j][b] = hn;
            g_a0[par ^ 1][d][1024 + j][b] = hn;    // h_rec for next step
        } else {
            g_afc[d * 512 + j][b] = hn;            // FC input
            g_a1[par ^ 1][d][1024 + j][b] = hn;    // h_rec for next step
        }
    }
}

// ---------------------------------------------------------------------------
// Single persistent kernel.
// ---------------------------------------------------------------------------
__global__ void __launch_bounds__(NTPB, 1) encoder_persistent(
    const float* __restrict__ in_seq,
    const float* __restrict__ W_ih, const float* __restrict__ W_hh,
    const float* __restrict__ b_ih, const float* __restrict__ b_hh,
    const float* __restrict__ W_fc, const float* __restrict__ b_fc,
    float* __restrict__ out)
{
    extern __shared__ float sm[];
    float* part = sm;                 // 48 KB
    float* ws   = sm + PART_F;        // 48 KB
    float* as   = sm + PART_F + WS_F; // 48 KB
    const int gtid = blockIdx.x * NTPB + threadIdx.x;

    // ===== init phase (runs every replay) =====
    // 1) xT[t][k][b] <- in_seq[b][t][k]
    for (int i = gtid; i < T_ * 512 * B_; i += NT) {
        int b = i & 31, k = (i >> 5) & 511, t = i >> 14;
        ((float*)g_xT)[i] = in_seq[((b << 9) | t) * 512 + k];
    }
    // 2) gate weights W_ih part: iterate (l,d,gate,j,k4)
    for (int i = gtid; i < 2 * 4096 * 256; i += NT) {
        int k4 = i & 255, rr = i >> 8;
        int l = rr >> 12, dgj = rr & 4095;
        int d = dgj >> 11, gate = (dgj >> 9) & 3, j = dgj & 511;
        int wrow = (l * 2 + d) * 2048 + gate * 512 + j;
        float4 w = ((const float4*)W_ih)[wrow * 256 + k4];
        int p = d * 2048 + j * 4 + gate;
        g_wT[l][k4 * 4 + 0][p] = w.x;
        g_wT[l][k4 * 4 + 1][p] = w.y;
        g_wT[l][k4 * 4 + 2][p] = w.z;
        g_wT[l][k4 * 4 + 3][p] = w.w;
    }
    // 3) gate weights W_hh part
    for (int i = gtid; i < 2 * 4096 * 128; i += NT) {
        int k4 = i & 127, rr = i >> 7;
        int l = rr >> 12, dgj = rr & 4095;
        int d = dgj >> 11, gate = (dgj >> 9) & 3, j = dgj & 511;
        int wrow = (l * 2 + d) * 2048 + gate * 512 + j;
        float4 w = ((const float4*)W_hh)[wrow * 128 + k4];
        int p = d * 2048 + j * 4 + gate;
        g_wT[l][1024 + k4 * 4 + 0][p] = w.x;
        g_wT[l][1024 + k4 * 4 + 1][p] = w.y;
        g_wT[l][1024 + k4 * 4 + 2][p] = w.z;
        g_wT[l][1024 + k4 * 4 + 3][p] = w.w;
    }
    // 4) FC weights: wfcT[k][o]
    for (int i = gtid; i < 512 * 256; i += NT) {
        int k4 = i & 255, o = i >> 8;
        float4 w = ((const float4*)W_fc)[o * 256 + k4];
        g_wfcT[k4 * 4 + 0][o] = w.x;
        g_wfcT[k4 * 4 + 1][o] = w.y;
        g_wfcT[k4 * 4 + 2][o] = w.z;
        g_wfcT[k4 * 4 + 3][o] = w.w;
    }
    // 5) biases (permuted)
    for (int i = gtid; i < 2 * 4096; i += NT) {
        int l = i >> 12, p = i & 4095;
        int d = p >> 11, j = (p >> 2) & 511, gate = p & 3;
        int wrow = (l * 2 + d) * 2048 + gate * 512 + j;
        g_bias[l][p] = b_ih[wrow] + b_hh[wrow];
    }
    // 6) zero initial state: a0[0] prev+hrec, a1[0] hrec, g_c
    for (int i = gtid; i < 2 * 1024 * B_; i += NT) {
        int b = i & 31, kk = (i >> 5) & 1023, d = i >> 15;
        g_a0[0][d][512 + kk][b] = 0.0f;
    }
    for (int i = gtid; i < 2 * 512 * B_; i += NT) {
        int b = i & 31, kk = (i >> 5) & 511, d = i >> 14;
        g_a1[0][d][1024 + kk][b] = 0.0f;
    }
    for (int i = gtid; i < 2 * 2 * LH_ * B_; i += NT) ((float*)g_c)[i] = 0.0f;
    // 7) x_0 into a0[0]
    for (int i = gtid; i < 512 * B_; i += NT) {
        int b = i & 31, k = i >> 5;
        float v = in_seq[(b << 18) + k];   // t = 0
        g_a0[0][0][k][b] = v;
        g_a0[0][1][k][b] = v;
    }
    gbar();

    // ===== time loop =====
    for (int t = 0; t < T_; t++) {
        const int par = t & 1;

        gate_stage<0>(par, part, ws, as);
        gbar();
        gate_stage<1>(par, part, ws, as);
        gbar();

        // FC head (blocks 0..63) + x_{t+1} copy (blocks 64..147)
        const int blk = blockIdx.x;
        if (blk < 64) {
            const int tid = threadIdx.x;
            if (tid < 512) {
                const int sub = tid & 15;
                const int slice = tid >> 4;          // 0..31, 32 k each
                const int bgrp = sub & 7;
                const int rowgrp = sub >> 3;         // 0..1
                const float4* __restrict__ w4 = (const float4*)
                    (&g_wfcT[slice * 32][blk * 8 + rowgrp * 4]);
                const float4* __restrict__ a4 = (const float4*)
                    (&g_afc[slice * 32][bgrp * 4]);
                float c00=0,c01=0,c02=0,c03=0, c10=0,c11=0,c12=0,c13=0;
                float c20=0,c21=0,c22=0,c23=0, c30=0,c31=0,c32=0,c33=0;
                #pragma unroll 8
                for (int i = 0; i < 32; i++) {
                    float4 w = w4[i * 128];          // wfcT row stride = 512
                    float4 a = a4[i * 8];
                    c00 += w.x*a.x; c01 += w.x*a.y; c02 += w.x*a.z; c03 += w.x*a.w;
                    c10 += w.y*a.x; c11 += w.y*a.y; c12 += w.y*a.z; c13 += w.y*a.w;
                    c20 += w.z*a.x; c21 += w.z*a.y; c22 += w.z*a.z; c23 += w.z*a.w;
                    c30 += w.w*a.x; c31 += w.w*a.y; c32 += w.w*a.z; c33 += w.w*a.w;
                }
                float4* p4 = (float4*)part;
                int base = (slice * 8 + rowgrp * 4) * 32 + bgrp * 4;
                p4[(base >> 2) + 0*8] = make_float4(c00, c01, c02, c03);
                p4[(base >> 2) + 1*8] = make_float4(c10, c11, c12, c13);
                p4[(base >> 2) + 2*8] = make_float4(c20, c21, c22, c23);
                p4[(base >> 2) + 3*8] = make_float4(c30, c31, c32, c33);
            }
            __syncthreads();
            if (threadIdx.x < 256) {
                const int r = threadIdx.x >> 5;
                const int b = threadIdx.x & 31;
                const int o = blk * 8 + r;
                float v = b_fc[o];
                #pragma unroll
                for (int s = 0; s < 32; s++) v += part[(s * 8 + r) * 32 + b];
                out[((b << 9) | t) * 512 + o] = v;            // outputs[b][t][o]
                g_a0[par ^ 1][0][512 + o][b] = v;             // prev for next step
                g_a0[par ^ 1][1][512 + o][b] = v;
            }
        } else if (t + 1 < T_) {
            // copy x_{t+1} into next-parity act buffers (both dirs)
            int idx = (blk - 64) * NTPB + threadIdx.x;
            if (idx < 4096) {                                 // 512*32/4 float4s
                const float4* xs = (const float4*)(&g_xT[t + 1][0][0]);
                float4 v = xs[idx];
                ((float4*)(&g_a0[par ^ 1][0][0][0]))[idx] = v;
                ((float4*)(&g_a0[par ^ 1][1][0][0]))[idx] = v;
            }
        }
        gbar();
    }

    // ===== final h_n / c_n =====
    // last step t=511 (par=1) wrote h_rec into buffers[0]
    for (int i = gtid; i < 65536; i += NT) {
        int b = i & 31, j = (i >> 5) & 511, d = (i >> 14) & 1, l = i >> 15;
        float h = (l == 0 ? g_a0[0][d][1024 + j][b] : g_a1[0][d][1024 + j][b]);
        float c = g_c[l][d][j][b];
        int ofs = (((l * 2 + d) * B_) + b) * LH_ + j;
        out[OUT_OFS + ofs] = h;
        out[OUT_OFS + HN_ELEMS + ofs] = c;
    }
}

// ---------------------------------------------------------------------------
// Inputs (metadata order): input_seq, input_lengths, W_ih, W_hh, b_ih, b_hh,
// W_fc, b_fc.
// ---------------------------------------------------------------------------
extern "C" void kernel_launch(void* const* d_in, const int* in_sizes, int n_in,
                              void* d_out, int out_size) {
    (void)in_sizes; (void)n_in; (void)out_size;
    cudaFuncSetAttribute(encoder_persistent,
                         cudaFuncAttributeMaxDynamicSharedMemorySize, SMEM_BYTES);
    encoder_persistent<<<NB, NTPB, SMEM_BYTES>>>(
        (const float*)d_in[0],
        (const float*)d_in[2], (const float*)d_in[3],
        (const float*)d_in[4], (const float*)d_in[5],
        (const float*)d_in[6], (const float*)d_in[7],
        (float*)d_out);
}